// round 1
// baseline (speedup 1.0000x reference)
#include <cuda_runtime.h>
#include <cuda_bf16.h>
#include <math.h>

// Problem constants
#define BATCH 8
#define CC 512          // channels (D)
#define NN 4096         // spatial (H*W)
#define RR 64           // rank
#define EPSV 1e-6f
#define NSTEPS 6

// ---------------- scratch (device globals; no allocation) ----------------
__device__ float g_H[BATCH * CC * NN];        // 64MB: lower output (NMF "x"), reused for cheese output
__device__ float g_T[BATCH * CC * NN];        // 64MB: ham output (bases @ coef^T)
__device__ float g_bases[BATCH * CC * RR];    // 1MB
__device__ float g_coef[BATCH * NN * RR];     // 8MB
__device__ float g_xtb[BATCH * NN * RR];      // 8MB
__device__ float g_coefT[BATCH * RR * NN];    // 8MB
__device__ float g_btb[BATCH * RR * RR];
__device__ float g_ctc[BATCH * RR * RR];
__device__ float g_xc[BATCH * CC * RR];       // 1MB
__device__ float g_xcp[BATCH * 8 * CC * RR];  // 8MB split-K partials for XC
__device__ float g_ctcp[BATCH * 16 * RR * RR];// 2MB split-K partials for CTC

// ---------------- bases l2-normalize over D ----------------
__global__ void k_norm_bases(const float* __restrict__ b0) {
    int b = blockIdx.x;
    __shared__ float part[8][64];
    __shared__ float inv[64];
    int r = threadIdx.x & 63;
    int g = threadIdx.x >> 6;   // 0..7
    float s = 0.f;
    for (int d = g; d < CC; d += 8) {
        float v = b0[((size_t)b * CC + d) * RR + r];
        s += v * v;
    }
    part[g][r] = s;
    __syncthreads();
    if (g == 0) {
        float t = 0.f;
        #pragma unroll
        for (int i = 0; i < 8; i++) t += part[i][r];
        inv[r] = 1.0f / fmaxf(sqrtf(t), 1e-12f);
    }
    __syncthreads();
    for (int d = g; d < CC; d += 8) {
        size_t idx = ((size_t)b * CC + d) * RR + r;
        g_bases[idx] = b0[idx] * inv[r];
    }
}

// ---------------- big GEMM: C[b] = op(A[b] @ B[b]) ----------------
// A: [512 x K] row-major (aStride per batch, 0 = shared), B: [K x 4096] row-major,
// C: [512 x 4096]. MODE 0: relu(acc+bias[m]); MODE 1: relu(sh*acc + ss*X); MODE 2: acc.
#define LOADA(buf, k0)                                                          \
    {                                                                           \
        _Pragma("unroll")                                                       \
        for (int p = 0; p < 2; p++) {                                           \
            int r_ = arow + p * 64;                                             \
            float4 v = *(const float4*)(Ab + (size_t)(m0 + r_) * K + (k0) + acol);\
            As[buf][acol + 0][r_] = v.x;                                        \
            As[buf][acol + 1][r_] = v.y;                                        \
            As[buf][acol + 2][r_] = v.z;                                        \
            As[buf][acol + 3][r_] = v.w;                                        \
        }                                                                       \
    }
#define LOADB(buf, k0)                                                          \
    {                                                                           \
        _Pragma("unroll")                                                       \
        for (int p = 0; p < 2; p++) {                                           \
            int r_ = brow + p * 8;                                              \
            float4 v = *(const float4*)(Bb + (size_t)((k0) + r_) * NN + n0 + bcol);\
            *(float4*)&Bs[buf][r_][bcol] = v;                                   \
        }                                                                       \
    }

template <int MODE>
__global__ void __launch_bounds__(256) k_gemm512(
    const float* __restrict__ A, size_t aStride, int K,
    const float* __restrict__ Bm, size_t bStride,
    float* __restrict__ Cm,
    const float* __restrict__ bias,
    const float* __restrict__ X,
    const float* __restrict__ sH, const float* __restrict__ sS)
{
    int b  = blockIdx.z;
    int m0 = blockIdx.y * 128;
    int n0 = blockIdx.x * 128;
    const float* Ab = A + (size_t)b * aStride;
    const float* Bb = Bm + (size_t)b * bStride;
    float* Cb = Cm + (size_t)b * CC * NN;

    __shared__ float As[2][16][132];
    __shared__ float Bs[2][16][128];

    int t = threadIdx.x;
    int arow = t >> 2;
    int acol = (t & 3) * 4;
    int brow = t >> 5;
    int bcol = (t & 31) * 4;
    int tm = (t >> 4) * 8;
    int tn = (t & 15) * 8;

    float acc[8][8];
    #pragma unroll
    for (int i = 0; i < 8; i++)
        #pragma unroll
        for (int j = 0; j < 8; j++) acc[i][j] = 0.f;

    LOADA(0, 0);
    LOADB(0, 0);
    __syncthreads();
    int ntiles = K / 16;
    for (int kt = 0; kt < ntiles; kt++) {
        int buf = kt & 1;
        if (kt + 1 < ntiles) {
            LOADA(buf ^ 1, (kt + 1) * 16);
            LOADB(buf ^ 1, (kt + 1) * 16);
        }
        #pragma unroll
        for (int k = 0; k < 16; k++) {
            float4 a0 = *(const float4*)&As[buf][k][tm];
            float4 a1 = *(const float4*)&As[buf][k][tm + 4];
            float4 bv0 = *(const float4*)&Bs[buf][k][tn];
            float4 bv1 = *(const float4*)&Bs[buf][k][tn + 4];
            float a[8] = {a0.x, a0.y, a0.z, a0.w, a1.x, a1.y, a1.z, a1.w};
            float bb[8] = {bv0.x, bv0.y, bv0.z, bv0.w, bv1.x, bv1.y, bv1.z, bv1.w};
            #pragma unroll
            for (int i = 0; i < 8; i++)
                #pragma unroll
                for (int j = 0; j < 8; j++)
                    acc[i][j] = fmaf(a[i], bb[j], acc[i][j]);
        }
        __syncthreads();
    }

    float sh = 0.f, ss = 0.f;
    if (MODE == 1) { sh = *sH; ss = *sS; }
    #pragma unroll
    for (int i = 0; i < 8; i++) {
        int m = m0 + tm + i;
        float bi = (MODE == 0) ? bias[m] : 0.f;
        float v[8];
        #pragma unroll
        for (int j = 0; j < 8; j++) v[j] = acc[i][j];
        if (MODE == 0) {
            #pragma unroll
            for (int j = 0; j < 8; j++) v[j] = fmaxf(v[j] + bi, 0.f);
        } else if (MODE == 1) {
            const float* Xr = X + ((size_t)b * CC + m) * NN + n0 + tn;
            float4 x0 = *(const float4*)&Xr[0];
            float4 x1 = *(const float4*)&Xr[4];
            float xv[8] = {x0.x, x0.y, x0.z, x0.w, x1.x, x1.y, x1.z, x1.w};
            #pragma unroll
            for (int j = 0; j < 8; j++) v[j] = fmaxf(sh * v[j] + ss * xv[j], 0.f);
        }
        float* Cr = Cb + (size_t)m * NN + n0 + tn;
        *(float4*)&Cr[0] = make_float4(v[0], v[1], v[2], v[3]);
        *(float4*)&Cr[4] = make_float4(v[4], v[5], v[6], v[7]);
    }
}

// ---------------- XTB: xtb[b][n][r] = sum_d H[b][d][n] * bases[b][d][r] ----------------
__global__ void __launch_bounds__(256) k_xtb() {
    int b = blockIdx.y;
    int n0 = blockIdx.x * 128;
    const float* H = g_H + (size_t)b * CC * NN;
    const float* Bp = g_bases + (size_t)b * CC * RR;
    __shared__ float Hs[32][128];
    __shared__ float Bsh[32][64];
    int t = threadIdx.x;
    int nI = (t & 15) * 8;
    int rI = (t >> 4) * 4;
    float acc[8][4];
    #pragma unroll
    for (int i = 0; i < 8; i++)
        #pragma unroll
        for (int j = 0; j < 4; j++) acc[i][j] = 0.f;

    for (int d0 = 0; d0 < CC; d0 += 32) {
        #pragma unroll
        for (int p = 0; p < 4; p++) {
            int dd = (t >> 5) + p * 8;
            int nn = (t & 31) * 4;
            *(float4*)&Hs[dd][nn] = *(const float4*)(H + (size_t)(d0 + dd) * NN + n0 + nn);
        }
        #pragma unroll
        for (int p = 0; p < 2; p++) {
            int dd = (t >> 4) + p * 16;
            int rr2 = (t & 15) * 4;
            *(float4*)&Bsh[dd][rr2] = *(const float4*)(Bp + (size_t)(d0 + dd) * RR + rr2);
        }
        __syncthreads();
        #pragma unroll
        for (int k = 0; k < 32; k++) {
            float4 a0 = *(const float4*)&Hs[k][nI];
            float4 a1 = *(const float4*)&Hs[k][nI + 4];
            float4 bv = *(const float4*)&Bsh[k][rI];
            float a[8] = {a0.x, a0.y, a0.z, a0.w, a1.x, a1.y, a1.z, a1.w};
            float bb[4] = {bv.x, bv.y, bv.z, bv.w};
            #pragma unroll
            for (int i = 0; i < 8; i++)
                #pragma unroll
                for (int j = 0; j < 4; j++)
                    acc[i][j] = fmaf(a[i], bb[j], acc[i][j]);
        }
        __syncthreads();
    }
    float* out = g_xtb + ((size_t)b * NN + n0) * RR;
    #pragma unroll
    for (int i = 0; i < 8; i++)
        *(float4*)&out[(size_t)(nI + i) * RR + rI] =
            make_float4(acc[i][0], acc[i][1], acc[i][2], acc[i][3]);
}

// ---------------- softmax over R (coef init) ----------------
__global__ void k_softmax() {
    int warp = (blockIdx.x * blockDim.x + threadIdx.x) >> 5;
    int lane = threadIdx.x & 31;
    if (warp >= BATCH * NN) return;
    const float* row = g_xtb + (size_t)warp * RR;
    float v0 = row[lane], v1 = row[lane + 32];
    float m = fmaxf(v0, v1);
    #pragma unroll
    for (int o = 16; o; o >>= 1) m = fmaxf(m, __shfl_xor_sync(0xffffffffu, m, o));
    float e0 = expf(v0 - m), e1 = expf(v1 - m);
    float s = e0 + e1;
    #pragma unroll
    for (int o = 16; o; o >>= 1) s += __shfl_xor_sync(0xffffffffu, s, o);
    float inv = 1.0f / s;
    float* orow = g_coef + (size_t)warp * RR;
    orow[lane] = e0 * inv;
    orow[lane + 32] = e1 * inv;
}

// ---------------- Gram: out[b][split] = M[b][split-range]^T @ M[b][split-range] ----------------
// M: [rowsTotal x 64] per batch (mStride per batch). Each block: 64x64 over kPerBlock rows.
__global__ void __launch_bounds__(256) k_ata(const float* __restrict__ Mb, size_t mStride,
                                             int kPerBlock, float* __restrict__ out, int nsplit) {
    int split = blockIdx.x;
    int b = blockIdx.y;
    const float* M = Mb + (size_t)b * mStride + (size_t)split * kPerBlock * RR;
    __shared__ float S[64][64];
    int t = threadIdx.x;
    int rI = (t & 15) * 4, sI = (t >> 4) * 4;
    float acc[4][4];
    #pragma unroll
    for (int i = 0; i < 4; i++)
        #pragma unroll
        for (int j = 0; j < 4; j++) acc[i][j] = 0.f;

    for (int k0 = 0; k0 < kPerBlock; k0 += 64) {
        #pragma unroll
        for (int p = 0; p < 4; p++) {
            int kr = (t >> 4) + p * 16;
            *(float4*)&S[kr][(t & 15) * 4] = *(const float4*)(M + (size_t)(k0 + kr) * RR + (t & 15) * 4);
        }
        __syncthreads();
        #pragma unroll
        for (int k = 0; k < 64; k++) {
            float4 av = *(const float4*)&S[k][rI];
            float4 bv = *(const float4*)&S[k][sI];
            float a[4] = {av.x, av.y, av.z, av.w};
            float bb[4] = {bv.x, bv.y, bv.z, bv.w};
            #pragma unroll
            for (int i = 0; i < 4; i++)
                #pragma unroll
                for (int j = 0; j < 4; j++)
                    acc[i][j] = fmaf(a[i], bb[j], acc[i][j]);
        }
        __syncthreads();
    }
    float* o = out + ((size_t)b * nsplit + split) * (RR * RR);
    #pragma unroll
    for (int i = 0; i < 4; i++)
        *(float4*)&o[(size_t)(rI + i) * RR + sI] =
            make_float4(acc[i][0], acc[i][1], acc[i][2], acc[i][3]);
}

// ---------------- generic split reduce: out[b][i] = sum_s in[b][s][i] ----------------
__global__ void k_reduce(const float* __restrict__ in, float* __restrict__ out,
                         int sz, int nsplit) {
    int idx = blockIdx.x * blockDim.x + threadIdx.x;
    if (idx >= BATCH * sz) return;
    int b = idx / sz;
    int i = idx - b * sz;
    const float* p = in + (size_t)b * nsplit * sz + i;
    float s = 0.f;
    for (int k = 0; k < nsplit; k++) s += p[(size_t)k * sz];
    out[(size_t)b * sz + i] = s;
}

// ---------------- multiplicative update: M = M * num / (M @ sq + eps) ----------------
// M, num: [B][rows][64]; sq: [B][64][64]
__global__ void __launch_bounds__(512) k_mu_update(float* __restrict__ M,
                                                   const float* __restrict__ num,
                                                   const float* __restrict__ sq, int rows) {
    int b = blockIdx.y;
    int n0 = blockIdx.x * 8;
    __shared__ float sB[64][65];
    __shared__ float sc[8][64];
    int t = threadIdx.x;
    const float* q = sq + (size_t)b * RR * RR;
    for (int i = t; i < RR * RR; i += 512) sB[i >> 6][i & 63] = q[i];
    int rr = t >> 6;
    int r = t & 63;
    size_t base = ((size_t)b * rows + n0 + rr) * RR;
    float c = M[base + r];
    sc[rr][r] = c;
    __syncthreads();
    float den = EPSV;
    #pragma unroll
    for (int s = 0; s < 64; s++) den = fmaf(sc[rr][s], sB[s][r], den);
    M[base + r] = c * num[base + r] / den;
}

// ---------------- XC split-K partials: xc[b][d][r] = sum_n H[b][d][n]*coef[b][n][r] ----------------
__global__ void __launch_bounds__(256) k_xc_part() {
    int split = blockIdx.x;   // 0..7 (n ranges of 512)
    int dt = blockIdx.y;      // 0..7 (d tiles of 64)
    int b = blockIdx.z;
    int d0 = dt * 64;
    int ns0 = split * 512;
    const float* H = g_H + (size_t)b * CC * NN;
    const float* C = g_coef + (size_t)b * NN * RR;
    __shared__ float Hs[32][68];
    __shared__ float Cs[32][64];
    int t = threadIdx.x;
    int dI = (t & 15) * 4, rI = (t >> 4) * 4;
    float acc[4][4];
    #pragma unroll
    for (int i = 0; i < 4; i++)
        #pragma unroll
        for (int j = 0; j < 4; j++) acc[i][j] = 0.f;

    for (int k0 = 0; k0 < 512; k0 += 32) {
        #pragma unroll
        for (int p = 0; p < 2; p++) {
            int dr = (t >> 3) + p * 32;
            int nc = (t & 7) * 4;
            float4 v = *(const float4*)(H + (size_t)(d0 + dr) * NN + ns0 + k0 + nc);
            Hs[nc + 0][dr] = v.x;
            Hs[nc + 1][dr] = v.y;
            Hs[nc + 2][dr] = v.z;
            Hs[nc + 3][dr] = v.w;
        }
        #pragma unroll
        for (int p = 0; p < 2; p++) {
            int nr = (t >> 4) + p * 16;
            int rc = (t & 15) * 4;
            *(float4*)&Cs[nr][rc] = *(const float4*)(C + (size_t)(ns0 + k0 + nr) * RR + rc);
        }
        __syncthreads();
        #pragma unroll
        for (int k = 0; k < 32; k++) {
            float4 av = *(const float4*)&Hs[k][dI];
            float4 bv = *(const float4*)&Cs[k][rI];
            float a[4] = {av.x, av.y, av.z, av.w};
            float bb[4] = {bv.x, bv.y, bv.z, bv.w};
            #pragma unroll
            for (int i = 0; i < 4; i++)
                #pragma unroll
                for (int j = 0; j < 4; j++)
                    acc[i][j] = fmaf(a[i], bb[j], acc[i][j]);
        }
        __syncthreads();
    }
    float* out = g_xcp + (((size_t)b * 8 + split) * CC + d0) * RR;
    #pragma unroll
    for (int i = 0; i < 4; i++)
        *(float4*)&out[(size_t)(dI + i) * RR + rI] =
            make_float4(acc[i][0], acc[i][1], acc[i][2], acc[i][3]);
}

// ---------------- coef transpose: coefT[b][r][n] = coef[b][n][r] ----------------
__global__ void k_transpose() {
    __shared__ float tile[32][33];
    int b = blockIdx.z;
    int n0 = blockIdx.x * 32, r0 = blockIdx.y * 32;
    const float* C = g_coef + (size_t)b * NN * RR;
    float* T = g_coefT + (size_t)b * RR * NN;
    int tx = threadIdx.x & 31, ty = threadIdx.x >> 5;  // 32 x 8
    #pragma unroll
    for (int p = 0; p < 4; p++) {
        int n = n0 + ty + p * 8;
        tile[ty + p * 8][tx] = C[(size_t)n * RR + r0 + tx];
    }
    __syncthreads();
    #pragma unroll
    for (int p = 0; p < 4; p++) {
        int r = r0 + ty + p * 8;
        T[(size_t)r * NN + n0 + tx] = tile[tx][ty + p * 8];
    }
}

// ---------------- host orchestration ----------------
extern "C" void kernel_launch(void* const* d_in, const int* in_sizes, int n_in,
                              void* d_out, int out_size) {
    const float* x        = (const float*)d_in[0];
    const float* bases0   = (const float*)d_in[1];
    const float* w_lower  = (const float*)d_in[2];
    const float* b_lower  = (const float*)d_in[3];
    const float* w_cheese = (const float*)d_in[4];
    const float* b_cheese = (const float*)d_in[5];
    const float* w_upper  = (const float*)d_in[6];
    const float* c_short  = (const float*)d_in[7];
    const float* c_ham    = (const float*)d_in[8];
    float* out = (float*)d_out;

    float *H, *T, *bases, *coef, *xtb, *coefT, *btb, *ctc, *xc, *xcp, *ctcp;
    cudaGetSymbolAddress((void**)&H, g_H);
    cudaGetSymbolAddress((void**)&T, g_T);
    cudaGetSymbolAddress((void**)&bases, g_bases);
    cudaGetSymbolAddress((void**)&coef, g_coef);
    cudaGetSymbolAddress((void**)&xtb, g_xtb);
    cudaGetSymbolAddress((void**)&coefT, g_coefT);
    cudaGetSymbolAddress((void**)&btb, g_btb);
    cudaGetSymbolAddress((void**)&ctc, g_ctc);
    cudaGetSymbolAddress((void**)&xc, g_xc);
    cudaGetSymbolAddress((void**)&xcp, g_xcp);
    cudaGetSymbolAddress((void**)&ctcp, g_ctcp);

    dim3 gemmGrid(NN / 128, CC / 128, BATCH);
    dim3 xtbGrid(NN / 128, BATCH);

    // bases = l2norm(bases0)
    k_norm_bases<<<BATCH, 512>>>(bases0);
    // H = relu(W_lower @ X + b_lower)
    k_gemm512<0><<<gemmGrid, 256>>>(w_lower, 0, CC, x, (size_t)CC * NN, H,
                                    b_lower, nullptr, nullptr, nullptr);
    // coef = softmax(H^T @ bases)
    k_xtb<<<xtbGrid, 256>>>();
    k_softmax<<<(BATCH * NN) / 8, 256>>>();

    for (int it = 0; it < NSTEPS; it++) {
        if (it > 0) k_xtb<<<xtbGrid, 256>>>();           // bases unchanged on first iter
        k_ata<<<dim3(1, BATCH), 256>>>(bases, (size_t)CC * RR, CC, btb, 1);
        k_mu_update<<<dim3(NN / 8, BATCH), 512>>>(coef, xtb, btb, NN);
        k_xc_part<<<dim3(8, 8, BATCH), 256>>>();
        k_reduce<<<(BATCH * CC * RR + 255) / 256, 256>>>(xcp, xc, CC * RR, 8);
        k_ata<<<dim3(16, BATCH), 256>>>(coef, (size_t)NN * RR, 256, ctcp, 16);
        k_reduce<<<(BATCH * RR * RR + 255) / 256, 256>>>(ctcp, ctc, RR * RR, 16);
        k_mu_update<<<dim3(CC / 8, BATCH), 512>>>(bases, xc, ctc, CC);
    }
    // differentiable coef refinement (one more coef update)
    k_xtb<<<xtbGrid, 256>>>();
    k_ata<<<dim3(1, BATCH), 256>>>(bases, (size_t)CC * RR, CC, btb, 1);
    k_mu_update<<<dim3(NN / 8, BATCH), 512>>>(coef, xtb, btb, NN);

    // ham out: T = bases @ coef^T
    k_transpose<<<dim3(NN / 32, RR / 32, BATCH), 256>>>();
    k_gemm512<2><<<gemmGrid, 256>>>(bases, (size_t)CC * RR, RR, coefT, (size_t)RR * NN, T,
                                    nullptr, nullptr, nullptr, nullptr);
    // H = relu(W_cheese @ T + b_cheese)
    k_gemm512<0><<<gemmGrid, 256>>>(w_cheese, 0, CC, T, (size_t)CC * NN, H,
                                    b_cheese, nullptr, nullptr, nullptr);
    // out = relu(c_ham * (W_upper @ H) + c_short * x)
    k_gemm512<1><<<gemmGrid, 256>>>(w_upper, 0, CC, H, (size_t)CC * NN, out,
                                    nullptr, x, c_ham, c_short);
    (void)in_sizes; (void)n_in; (void)out_size;
}

// round 2
// speedup vs baseline: 1.5841x; 1.5841x over previous
#include <cuda_runtime.h>
#include <cuda_bf16.h>
#include <math.h>

// Problem constants
#define BATCH 8
#define CC 512          // channels (D)
#define NN 4096         // spatial (H*W)
#define RR 64           // rank
#define EPSV 1e-6f
#define NSTEPS 6

// ---------------- scratch (device globals; no allocation) ----------------
__device__ float g_H[BATCH * CC * NN];        // 64MB: lower output (NMF "x"), reused for cheese output
__device__ float g_T[BATCH * CC * NN];        // 64MB: ham output (bases @ coef^T)
__device__ float g_bases[BATCH * CC * RR];    // 1MB
__device__ float g_coef[BATCH * NN * RR];     // 8MB
__device__ float g_xtb[BATCH * NN * RR];      // 8MB
__device__ float g_coefT[BATCH * RR * NN];    // 8MB
__device__ float g_btb[BATCH * RR * RR];
__device__ float g_ctc[BATCH * RR * RR];
__device__ float g_xc[BATCH * CC * RR];       // 1MB
__device__ float g_xcp[BATCH * 8 * CC * RR];  // 8MB split-K partials for XC
__device__ float g_ctcp[BATCH * 16 * RR * RR];// 2MB split-K partials for CTC

// ---------------- bases l2-normalize over D ----------------
__global__ void k_norm_bases(const float* __restrict__ b0) {
    int b = blockIdx.x;
    __shared__ float part[8][64];
    __shared__ float inv[64];
    int r = threadIdx.x & 63;
    int g = threadIdx.x >> 6;   // 0..7
    float s = 0.f;
    for (int d = g; d < CC; d += 8) {
        float v = b0[((size_t)b * CC + d) * RR + r];
        s += v * v;
    }
    part[g][r] = s;
    __syncthreads();
    if (g == 0) {
        float t = 0.f;
        #pragma unroll
        for (int i = 0; i < 8; i++) t += part[i][r];
        inv[r] = 1.0f / fmaxf(sqrtf(t), 1e-12f);
    }
    __syncthreads();
    for (int d = g; d < CC; d += 8) {
        size_t idx = ((size_t)b * CC + d) * RR + r;
        g_bases[idx] = b0[idx] * inv[r];
    }
}

// ---------------- big GEMM: C[b] = op(A[b] @ B[b]) ----------------
// A: [512 x K] row-major (aStride per batch, 0 = shared), B: [K x 4096] row-major,
// C: [512 x 4096]. MODE 0: relu(acc+bias[m]); MODE 1: relu(sh*acc + ss*X); MODE 2: acc.
#define LOADA(buf, k0)                                                          \
    {                                                                           \
        _Pragma("unroll")                                                       \
        for (int p = 0; p < 2; p++) {                                           \
            int r_ = arow + p * 64;                                             \
            float4 v = *(const float4*)(Ab + (size_t)(m0 + r_) * K + (k0) + acol);\
            As[buf][acol + 0][r_] = v.x;                                        \
            As[buf][acol + 1][r_] = v.y;                                        \
            As[buf][acol + 2][r_] = v.z;                                        \
            As[buf][acol + 3][r_] = v.w;                                        \
        }                                                                       \
    }
#define LOADB(buf, k0)                                                          \
    {                                                                           \
        _Pragma("unroll")                                                       \
        for (int p = 0; p < 2; p++) {                                           \
            int r_ = brow + p * 8;                                              \
            float4 v = *(const float4*)(Bb + (size_t)((k0) + r_) * NN + n0 + bcol);\
            *(float4*)&Bs[buf][r_][bcol] = v;                                   \
        }                                                                       \
    }

template <int MODE>
__global__ void __launch_bounds__(256) k_gemm512(
    const float* __restrict__ A, size_t aStride, int K,
    const float* __restrict__ Bm, size_t bStride,
    float* __restrict__ Cm,
    const float* __restrict__ bias,
    const float* __restrict__ X,
    const float* __restrict__ sH, const float* __restrict__ sS)
{
    int b  = blockIdx.z;
    int m0 = blockIdx.y * 128;
    int n0 = blockIdx.x * 128;
    const float* Ab = A + (size_t)b * aStride;
    const float* Bb = Bm + (size_t)b * bStride;
    float* Cb = Cm + (size_t)b * CC * NN;

    __shared__ float As[2][16][132];
    __shared__ float Bs[2][16][128];

    int t = threadIdx.x;
    int arow = t >> 2;
    int acol = (t & 3) * 4;
    int brow = t >> 5;
    int bcol = (t & 31) * 4;
    int tm = (t >> 4) * 8;
    int tn = (t & 15) * 8;

    float acc[8][8];
    #pragma unroll
    for (int i = 0; i < 8; i++)
        #pragma unroll
        for (int j = 0; j < 8; j++) acc[i][j] = 0.f;

    LOADA(0, 0);
    LOADB(0, 0);
    __syncthreads();
    int ntiles = K / 16;
    for (int kt = 0; kt < ntiles; kt++) {
        int buf = kt & 1;
        if (kt + 1 < ntiles) {
            LOADA(buf ^ 1, (kt + 1) * 16);
            LOADB(buf ^ 1, (kt + 1) * 16);
        }
        #pragma unroll
        for (int k = 0; k < 16; k++) {
            float4 a0 = *(const float4*)&As[buf][k][tm];
            float4 a1 = *(const float4*)&As[buf][k][tm + 4];
            float4 bv0 = *(const float4*)&Bs[buf][k][tn];
            float4 bv1 = *(const float4*)&Bs[buf][k][tn + 4];
            float a[8] = {a0.x, a0.y, a0.z, a0.w, a1.x, a1.y, a1.z, a1.w};
            float bb[8] = {bv0.x, bv0.y, bv0.z, bv0.w, bv1.x, bv1.y, bv1.z, bv1.w};
            #pragma unroll
            for (int i = 0; i < 8; i++)
                #pragma unroll
                for (int j = 0; j < 8; j++)
                    acc[i][j] = fmaf(a[i], bb[j], acc[i][j]);
        }
        __syncthreads();
    }

    float sh = 0.f, ss = 0.f;
    if (MODE == 1) { sh = *sH; ss = *sS; }
    #pragma unroll
    for (int i = 0; i < 8; i++) {
        int m = m0 + tm + i;
        float bi = (MODE == 0) ? bias[m] : 0.f;
        float v[8];
        #pragma unroll
        for (int j = 0; j < 8; j++) v[j] = acc[i][j];
        if (MODE == 0) {
            #pragma unroll
            for (int j = 0; j < 8; j++) v[j] = fmaxf(v[j] + bi, 0.f);
        } else if (MODE == 1) {
            const float* Xr = X + ((size_t)b * CC + m) * NN + n0 + tn;
            float4 x0 = *(const float4*)&Xr[0];
            float4 x1 = *(const float4*)&Xr[4];
            float xv[8] = {x0.x, x0.y, x0.z, x0.w, x1.x, x1.y, x1.z, x1.w};
            #pragma unroll
            for (int j = 0; j < 8; j++) v[j] = fmaxf(sh * v[j] + ss * xv[j], 0.f);
        }
        float* Cr = Cb + (size_t)m * NN + n0 + tn;
        *(float4*)&Cr[0] = make_float4(v[0], v[1], v[2], v[3]);
        *(float4*)&Cr[4] = make_float4(v[4], v[5], v[6], v[7]);
    }
}

// ---------------- XTB: xtb[b][n][r] = sum_d H[b][d][n] * bases[b][d][r] ----------------
__global__ void __launch_bounds__(256) k_xtb() {
    int b = blockIdx.y;
    int n0 = blockIdx.x * 128;
    const float* H = g_H + (size_t)b * CC * NN;
    const float* Bp = g_bases + (size_t)b * CC * RR;
    __shared__ float Hs[32][128];
    __shared__ float Bsh[32][64];
    int t = threadIdx.x;
    int nI = (t & 15) * 8;
    int rI = (t >> 4) * 4;
    float acc[8][4];
    #pragma unroll
    for (int i = 0; i < 8; i++)
        #pragma unroll
        for (int j = 0; j < 4; j++) acc[i][j] = 0.f;

    for (int d0 = 0; d0 < CC; d0 += 32) {
        #pragma unroll
        for (int p = 0; p < 4; p++) {
            int dd = (t >> 5) + p * 8;
            int nn = (t & 31) * 4;
            *(float4*)&Hs[dd][nn] = *(const float4*)(H + (size_t)(d0 + dd) * NN + n0 + nn);
        }
        #pragma unroll
        for (int p = 0; p < 2; p++) {
            int dd = (t >> 4) + p * 16;
            int rr2 = (t & 15) * 4;
            *(float4*)&Bsh[dd][rr2] = *(const float4*)(Bp + (size_t)(d0 + dd) * RR + rr2);
        }
        __syncthreads();
        #pragma unroll
        for (int k = 0; k < 32; k++) {
            float4 a0 = *(const float4*)&Hs[k][nI];
            float4 a1 = *(const float4*)&Hs[k][nI + 4];
            float4 bv = *(const float4*)&Bsh[k][rI];
            float a[8] = {a0.x, a0.y, a0.z, a0.w, a1.x, a1.y, a1.z, a1.w};
            float bb[4] = {bv.x, bv.y, bv.z, bv.w};
            #pragma unroll
            for (int i = 0; i < 8; i++)
                #pragma unroll
                for (int j = 0; j < 4; j++)
                    acc[i][j] = fmaf(a[i], bb[j], acc[i][j]);
        }
        __syncthreads();
    }
    float* out = g_xtb + ((size_t)b * NN + n0) * RR;
    #pragma unroll
    for (int i = 0; i < 8; i++)
        *(float4*)&out[(size_t)(nI + i) * RR + rI] =
            make_float4(acc[i][0], acc[i][1], acc[i][2], acc[i][3]);
}

// ---------------- softmax over R (coef init) ----------------
__global__ void k_softmax() {
    int warp = (blockIdx.x * blockDim.x + threadIdx.x) >> 5;
    int lane = threadIdx.x & 31;
    if (warp >= BATCH * NN) return;
    const float* row = g_xtb + (size_t)warp * RR;
    float v0 = row[lane], v1 = row[lane + 32];
    float m = fmaxf(v0, v1);
    #pragma unroll
    for (int o = 16; o; o >>= 1) m = fmaxf(m, __shfl_xor_sync(0xffffffffu, m, o));
    float e0 = expf(v0 - m), e1 = expf(v1 - m);
    float s = e0 + e1;
    #pragma unroll
    for (int o = 16; o; o >>= 1) s += __shfl_xor_sync(0xffffffffu, s, o);
    float inv = 1.0f / s;
    float* orow = g_coef + (size_t)warp * RR;
    orow[lane] = e0 * inv;
    orow[lane + 32] = e1 * inv;
}

// ---------------- Gram: out[b][split] = M[b][split-range]^T @ M[b][split-range] ----------------
// M: [rowsTotal x 64] per batch (mStride per batch). Each block: 64x64 over kPerBlock rows.
__global__ void __launch_bounds__(256) k_ata(const float* __restrict__ Mb, size_t mStride,
                                             int kPerBlock, float* __restrict__ out, int nsplit) {
    int split = blockIdx.x;
    int b = blockIdx.y;
    const float* M = Mb + (size_t)b * mStride + (size_t)split * kPerBlock * RR;
    __shared__ float S[64][64];
    int t = threadIdx.x;
    int rI = (t & 15) * 4, sI = (t >> 4) * 4;
    float acc[4][4];
    #pragma unroll
    for (int i = 0; i < 4; i++)
        #pragma unroll
        for (int j = 0; j < 4; j++) acc[i][j] = 0.f;

    for (int k0 = 0; k0 < kPerBlock; k0 += 64) {
        #pragma unroll
        for (int p = 0; p < 4; p++) {
            int kr = (t >> 4) + p * 16;
            *(float4*)&S[kr][(t & 15) * 4] = *(const float4*)(M + (size_t)(k0 + kr) * RR + (t & 15) * 4);
        }
        __syncthreads();
        #pragma unroll
        for (int k = 0; k < 64; k++) {
            float4 av = *(const float4*)&S[k][rI];
            float4 bv = *(const float4*)&S[k][sI];
            float a[4] = {av.x, av.y, av.z, av.w};
            float bb[4] = {bv.x, bv.y, bv.z, bv.w};
            #pragma unroll
            for (int i = 0; i < 4; i++)
                #pragma unroll
                for (int j = 0; j < 4; j++)
                    acc[i][j] = fmaf(a[i], bb[j], acc[i][j]);
        }
        __syncthreads();
    }
    float* o = out + ((size_t)b * nsplit + split) * (RR * RR);
    #pragma unroll
    for (int i = 0; i < 4; i++)
        *(float4*)&o[(size_t)(rI + i) * RR + sI] =
            make_float4(acc[i][0], acc[i][1], acc[i][2], acc[i][3]);
}

// ---------------- generic split reduce: out[b][i] = sum_s in[b][s][i] ----------------
__global__ void k_reduce(const float* __restrict__ in, float* __restrict__ out,
                         int sz, int nsplit) {
    int idx = blockIdx.x * blockDim.x + threadIdx.x;
    if (idx >= BATCH * sz) return;
    int b = idx / sz;
    int i = idx - b * sz;
    const float* p = in + (size_t)b * nsplit * sz + i;
    float s = 0.f;
    for (int k = 0; k < nsplit; k++) s += p[(size_t)k * sz];
    out[(size_t)b * sz + i] = s;
}

// ---------------- multiplicative update: M = M * num / (M @ sq + eps) ----------------
// M, num: [B][rows][64]; sq: [B][64][64]
__global__ void __launch_bounds__(512) k_mu_update(float* __restrict__ M,
                                                   const float* __restrict__ num,
                                                   const float* __restrict__ sq, int rows) {
    int b = blockIdx.y;
    int n0 = blockIdx.x * 8;
    __shared__ float sB[64][65];
    __shared__ float sc[8][64];
    int t = threadIdx.x;
    const float* q = sq + (size_t)b * RR * RR;
    for (int i = t; i < RR * RR; i += 512) sB[i >> 6][i & 63] = q[i];
    int rr = t >> 6;
    int r = t & 63;
    size_t base = ((size_t)b * rows + n0 + rr) * RR;
    float c = M[base + r];
    sc[rr][r] = c;
    __syncthreads();
    float den = EPSV;
    #pragma unroll
    for (int s = 0; s < 64; s++) den = fmaf(sc[rr][s], sB[s][r], den);
    M[base + r] = c * num[base + r] / den;
}

// ---------------- XC split-K partials: xc[b][d][r] = sum_n H[b][d][n]*coef[b][n][r] ----------------
__global__ void __launch_bounds__(256) k_xc_part() {
    int split = blockIdx.x;   // 0..7 (n ranges of 512)
    int dt = blockIdx.y;      // 0..7 (d tiles of 64)
    int b = blockIdx.z;
    int d0 = dt * 64;
    int ns0 = split * 512;
    const float* H = g_H + (size_t)b * CC * NN;
    const float* C = g_coef + (size_t)b * NN * RR;
    __shared__ float Hs[32][68];
    __shared__ float Cs[32][64];
    int t = threadIdx.x;
    int dI = (t & 15) * 4, rI = (t >> 4) * 4;
    float acc[4][4];
    #pragma unroll
    for (int i = 0; i < 4; i++)
        #pragma unroll
        for (int j = 0; j < 4; j++) acc[i][j] = 0.f;

    for (int k0 = 0; k0 < 512; k0 += 32) {
        #pragma unroll
        for (int p = 0; p < 2; p++) {
            int dr = (t >> 3) + p * 32;
            int nc = (t & 7) * 4;
            float4 v = *(const float4*)(H + (size_t)(d0 + dr) * NN + ns0 + k0 + nc);
            Hs[nc + 0][dr] = v.x;
            Hs[nc + 1][dr] = v.y;
            Hs[nc + 2][dr] = v.z;
            Hs[nc + 3][dr] = v.w;
        }
        #pragma unroll
        for (int p = 0; p < 2; p++) {
            int nr = (t >> 4) + p * 16;
            int rc = (t & 15) * 4;
            *(float4*)&Cs[nr][rc] = *(const float4*)(C + (size_t)(ns0 + k0 + nr) * RR + rc);
        }
        __syncthreads();
        #pragma unroll
        for (int k = 0; k < 32; k++) {
            float4 av = *(const float4*)&Hs[k][dI];
            float4 bv = *(const float4*)&Cs[k][rI];
            float a[4] = {av.x, av.y, av.z, av.w};
            float bb[4] = {bv.x, bv.y, bv.z, bv.w};
            #pragma unroll
            for (int i = 0; i < 4; i++)
                #pragma unroll
                for (int j = 0; j < 4; j++)
                    acc[i][j] = fmaf(a[i], bb[j], acc[i][j]);
        }
        __syncthreads();
    }
    float* out = g_xcp + (((size_t)b * 8 + split) * CC + d0) * RR;
    #pragma unroll
    for (int i = 0; i < 4; i++)
        *(float4*)&out[(size_t)(dI + i) * RR + rI] =
            make_float4(acc[i][0], acc[i][1], acc[i][2], acc[i][3]);
}

// ---------------- coef transpose: coefT[b][r][n] = coef[b][n][r] ----------------
__global__ void k_transpose() {
    __shared__ float tile[32][33];
    int b = blockIdx.z;
    int n0 = blockIdx.x * 32, r0 = blockIdx.y * 32;
    const float* C = g_coef + (size_t)b * NN * RR;
    float* T = g_coefT + (size_t)b * RR * NN;
    int tx = threadIdx.x & 31, ty = threadIdx.x >> 5;  // 32 x 8
    #pragma unroll
    for (int p = 0; p < 4; p++) {
        int n = n0 + ty + p * 8;
        tile[ty + p * 8][tx] = C[(size_t)n * RR + r0 + tx];
    }
    __syncthreads();
    #pragma unroll
    for (int p = 0; p < 4; p++) {
        int r = r0 + ty + p * 8;
        T[(size_t)r * NN + n0 + tx] = tile[tx][ty + p * 8];
    }
}

// ---------------- host orchestration ----------------
extern "C" void kernel_launch(void* const* d_in, const int* in_sizes, int n_in,
                              void* d_out, int out_size) {
    const float* x        = (const float*)d_in[0];
    const float* bases0   = (const float*)d_in[1];
    const float* w_lower  = (const float*)d_in[2];
    const float* b_lower  = (const float*)d_in[3];
    const float* w_cheese = (const float*)d_in[4];
    const float* b_cheese = (const float*)d_in[5];
    const float* w_upper  = (const float*)d_in[6];
    const float* c_short  = (const float*)d_in[7];
    const float* c_ham    = (const float*)d_in[8];
    float* out = (float*)d_out;

    float *H, *T, *bases, *coef, *xtb, *coefT, *btb, *ctc, *xc, *xcp, *ctcp;
    cudaGetSymbolAddress((void**)&H, g_H);
    cudaGetSymbolAddress((void**)&T, g_T);
    cudaGetSymbolAddress((void**)&bases, g_bases);
    cudaGetSymbolAddress((void**)&coef, g_coef);
    cudaGetSymbolAddress((void**)&xtb, g_xtb);
    cudaGetSymbolAddress((void**)&coefT, g_coefT);
    cudaGetSymbolAddress((void**)&btb, g_btb);
    cudaGetSymbolAddress((void**)&ctc, g_ctc);
    cudaGetSymbolAddress((void**)&xc, g_xc);
    cudaGetSymbolAddress((void**)&xcp, g_xcp);
    cudaGetSymbolAddress((void**)&ctcp, g_ctcp);

    dim3 gemmGrid(NN / 128, CC / 128, BATCH);
    dim3 xtbGrid(NN / 128, BATCH);

    // bases = l2norm(bases0)
    k_norm_bases<<<BATCH, 512>>>(bases0);
    // H = relu(W_lower @ X + b_lower)
    k_gemm512<0><<<gemmGrid, 256>>>(w_lower, 0, CC, x, (size_t)CC * NN, H,
                                    b_lower, nullptr, nullptr, nullptr);
    // coef = softmax(H^T @ bases)
    k_xtb<<<xtbGrid, 256>>>();
    k_softmax<<<(BATCH * NN) / 8, 256>>>();

    for (int it = 0; it < NSTEPS; it++) {
        if (it > 0) k_xtb<<<xtbGrid, 256>>>();           // bases unchanged on first iter
        k_ata<<<dim3(1, BATCH), 256>>>(bases, (size_t)CC * RR, CC, btb, 1);
        k_mu_update<<<dim3(NN / 8, BATCH), 512>>>(coef, xtb, btb, NN);
        k_xc_part<<<dim3(8, 8, BATCH), 256>>>();
        k_reduce<<<(BATCH * CC * RR + 255) / 256, 256>>>(xcp, xc, CC * RR, 8);
        k_ata<<<dim3(16, BATCH), 256>>>(coef, (size_t)NN * RR, 256, ctcp, 16);
        k_reduce<<<(BATCH * RR * RR + 255) / 256, 256>>>(ctcp, ctc, RR * RR, 16);
        k_mu_update<<<dim3(CC / 8, BATCH), 512>>>(bases, xc, ctc, CC);
    }
    // differentiable coef refinement (one more coef update)
    k_xtb<<<xtbGrid, 256>>>();
    k_ata<<<dim3(1, BATCH), 256>>>(bases, (size_t)CC * RR, CC, btb, 1);
    k_mu_update<<<dim3(NN / 8, BATCH), 512>>>(coef, xtb, btb, NN);

    // ham out: T = bases @ coef^T
    k_transpose<<<dim3(NN / 32, RR / 32, BATCH), 256>>>();
    k_gemm512<2><<<gemmGrid, 256>>>(bases, (size_t)CC * RR, RR, coefT, (size_t)RR * NN, T,
                                    nullptr, nullptr, nullptr, nullptr);
    // H = relu(W_cheese @ T + b_cheese)
    k_gemm512<0><<<gemmGrid, 256>>>(w_cheese, 0, CC, T, (size_t)CC * NN, H,
                                    b_cheese, nullptr, nullptr, nullptr);
    // out = relu(c_ham * (W_upper @ H) + c_short * x)
    k_gemm512<1><<<gemmGrid, 256>>>(w_upper, 0, CC, H, (size_t)CC * NN, out,
                                    nullptr, x, c_ham, c_short);
    (void)in_sizes; (void)n_in; (void)out_size;
}

// round 4
// speedup vs baseline: 2.9280x; 1.8484x over previous
#include <cuda_runtime.h>
#include <cuda_bf16.h>
#include <cstdint>
#include <math.h>

#define BATCH 8
#define CC 512
#define NN 4096
#define RR 64
#define EPSV 1e-6f
#define NSTEPS 6
typedef __nv_bfloat16 bf16;

__device__ __forceinline__ uint32_t smem_u32(const void* p) {
    uint32_t a;
    asm("{ .reg .u64 t; cvta.to.shared.u64 t, %1; cvt.u32.u64 %0, t; }" : "=r"(a) : "l"(p));
    return a;
}
__device__ __forceinline__ void ldsm4(uint32_t* d, uint32_t addr) {
    asm volatile("ldmatrix.sync.aligned.m8n8.x4.shared.b16 {%0,%1,%2,%3}, [%4];"
        : "=r"(d[0]), "=r"(d[1]), "=r"(d[2]), "=r"(d[3]) : "r"(addr));
}
__device__ __forceinline__ void ldsm2(uint32_t* d, uint32_t addr) {
    asm volatile("ldmatrix.sync.aligned.m8n8.x2.shared.b16 {%0,%1}, [%2];"
        : "=r"(d[0]), "=r"(d[1]) : "r"(addr));
}
__device__ __forceinline__ void mma16816(float* c, const uint32_t* a, const uint32_t* b) {
    asm volatile("mma.sync.aligned.m16n8k16.row.col.f32.bf16.bf16.f32 "
        "{%0,%1,%2,%3}, {%4,%5,%6,%7}, {%8,%9}, {%0,%1,%2,%3};"
        : "+f"(c[0]), "+f"(c[1]), "+f"(c[2]), "+f"(c[3])
        : "r"(a[0]), "r"(a[1]), "r"(a[2]), "r"(a[3]), "r"(b[0]), "r"(b[1]));
}

// -------- scratch --------
__device__ float g_bases[BATCH * CC * RR];
__device__ float g_coef[BATCH * NN * RR];
__device__ float g_xtb[BATCH * NN * RR];
__device__ float g_xc[BATCH * CC * RR];
__device__ float g_btb[BATCH * RR * RR];
__device__ float g_ctc[BATCH * RR * RR];
__device__ float g_ctcp[BATCH * 16 * RR * RR];
__device__ float g_xcp[BATCH * 8 * CC * RR];
__device__ bf16 g_WLh[CC * CC], g_WLl[CC * CC], g_WUh[CC * CC], g_WUl[CC * CC];
__device__ bf16 g_Xth[BATCH * NN * CC], g_Xtl[BATCH * NN * CC];
__device__ bf16 g_Hh[BATCH * CC * NN], g_Hl[BATCH * CC * NN];
__device__ bf16 g_Hth[BATCH * NN * CC], g_Htl[BATCH * NN * CC];
__device__ bf16 g_H2h[BATCH * NN * CC], g_H2l[BATCH * NN * CC];
__device__ bf16 g_cTh[BATCH * RR * NN], g_cTl[BATCH * RR * NN];
__device__ bf16 g_Ch[BATCH * NN * RR], g_Cl[BATCH * NN * RR];
__device__ bf16 g_bTh[BATCH * RR * CC], g_bTl[BATCH * RR * CC];
__device__ bf16 g_Wbh[BATCH * CC * RR], g_Wbl[BATCH * CC * RR];

// ============ mma.sync bf16x3 GEMM: D[m][n'] = sum_k A[m][k] * B[n'][k] ============
// 8 warps as 4(M) x 2(N); block tile 128 x TN; K chunk 32, double buffered.
// EPI 0: fp32 out (split-K aware). 1: relu(v+bias[row]) -> pairs row-major (stride NN)
//        AND transposed pairs (stride CC). 2: relu(v+bias[col]) -> pairs row-major stride CC.
// 3: fp32 relu(sH*v + sS*X).
template <int TN, int SPLITK, int EPI>
__global__ void __launch_bounds__(256) k_mma(
    const bf16* __restrict__ Ahi, const bf16* __restrict__ Alo, size_t aB, int aS,
    const bf16* __restrict__ Bhi, const bf16* __restrict__ Blo, size_t bB, int bS,
    int kLen,
    float* __restrict__ outF, size_t oB, int oS,
    bf16* __restrict__ oHi, bf16* __restrict__ oLo, const float* __restrict__ bias,
    bf16* __restrict__ tHi, bf16* __restrict__ tLo,
    const float* __restrict__ Xres, const float* __restrict__ sH, const float* __restrict__ sS)
{
    extern __shared__ char smem[];
    constexpr int NF = TN / 16;        // n-frags per warp (warp covers TN/2)
    constexpr int WN = TN / 2;
    constexpr int BP = TN / 64;        // B row-parts per thread in loads
    constexpr int SW = TN + 1;         // stage pad
    bf16* sAB = (bf16*)smem;           // A: [buf][pl][128][40] then B: [buf][pl][TN][40]
    const int BOFF = 2 * 2 * 128 * 40; // b16 offset of B region
    float* stage = (float*)smem;
    uint32_t smb = smem_u32(smem);

    int tid = threadIdx.x, lane = tid & 31, wid = tid >> 5;
    int wm = wid >> 1, wn = wid & 1;
    int b = blockIdx.z;
    int ks = (SPLITK > 1) ? blockIdx.x : 0;
    int n0 = (SPLITK > 1) ? 0 : blockIdx.x * TN;
    int m0 = blockIdx.y * 128;

    const bf16* A0 = Ahi + (size_t)b * aB + (size_t)m0 * aS + ks * kLen;
    const bf16* A1 = Alo + (size_t)b * aB + (size_t)m0 * aS + ks * kLen;
    const bf16* B0 = Bhi + (size_t)b * bB + (size_t)n0 * bS + ks * kLen;
    const bf16* B1 = Blo + (size_t)b * bB + (size_t)n0 * bS + ks * kLen;

    float c[2][NF][4];
    #pragma unroll
    for (int i = 0; i < 2; i++)
        #pragma unroll
        for (int j = 0; j < NF; j++)
            #pragma unroll
            for (int q = 0; q < 4; q++) c[i][j][q] = 0.f;

    uint4 pA[2][2], pB[BP][2];
    int lr = tid >> 2, lc = tid & 3;

    auto gload = [&](int koff) {
        #pragma unroll
        for (int p = 0; p < 2; p++) {
            size_t o = (size_t)(lr + p * 64) * aS + koff + lc * 8;
            pA[p][0] = *(const uint4*)(A0 + o);
            pA[p][1] = *(const uint4*)(A1 + o);
        }
        #pragma unroll
        for (int p = 0; p < BP; p++) {
            size_t o = (size_t)(lr + p * 64) * bS + koff + lc * 8;
            pB[p][0] = *(const uint4*)(B0 + o);
            pB[p][1] = *(const uint4*)(B1 + o);
        }
    };
    auto sstore = [&](int buf) {
        #pragma unroll
        for (int p = 0; p < 2; p++) {
            *(uint4*)&sAB[((buf * 2 + 0) * 128 + lr + p * 64) * 40 + lc * 8] = pA[p][0];
            *(uint4*)&sAB[((buf * 2 + 1) * 128 + lr + p * 64) * 40 + lc * 8] = pA[p][1];
        }
        #pragma unroll
        for (int p = 0; p < BP; p++) {
            *(uint4*)&sAB[BOFF + ((buf * 2 + 0) * TN + lr + p * 64) * 40 + lc * 8] = pB[p][0];
            *(uint4*)&sAB[BOFF + ((buf * 2 + 1) * TN + lr + p * 64) * 40 + lc * 8] = pB[p][1];
        }
    };
    auto compute = [&](int buf) {
        #pragma unroll
        for (int kk = 0; kk < 32; kk += 16) {
            uint32_t a[2][2][4];
            #pragma unroll
            for (int pl = 0; pl < 2; pl++)
                #pragma unroll
                for (int mf = 0; mf < 2; mf++) {
                    int row = wm * 32 + mf * 16 + (lane & 15);
                    ldsm4(a[pl][mf],
                          smb + 2u * (((buf * 2 + pl) * 128 + row) * 40 + kk + (lane >> 4) * 8));
                }
            #pragma unroll
            for (int nf = 0; nf < NF; nf++) {
                uint32_t bb[2][2];
                #pragma unroll
                for (int pl = 0; pl < 2; pl++) {
                    int rowb = wn * WN + nf * 8 + (lane & 7);
                    ldsm2(bb[pl],
                          smb + 2u * (BOFF + ((buf * 2 + pl) * TN + rowb) * 40 + kk + ((lane >> 3) & 1) * 8));
                }
                #pragma unroll
                for (int mf = 0; mf < 2; mf++) {
                    mma16816(c[mf][nf], a[0][mf], bb[0]);   // hi*hi
                    mma16816(c[mf][nf], a[0][mf], bb[1]);   // hi*lo
                    mma16816(c[mf][nf], a[1][mf], bb[0]);   // lo*hi
                }
            }
        }
    };

    gload(0);
    sstore(0);
    __syncthreads();
    int nch = kLen / 32;
    for (int ch = 0; ch < nch; ch++) {
        if (ch + 1 < nch) gload((ch + 1) * 32);
        compute(ch & 1);
        if (ch + 1 < nch) sstore((ch + 1) & 1);
        __syncthreads();
    }

    // ---- stage C tile in smem ----
    #pragma unroll
    for (int mf = 0; mf < 2; mf++)
        #pragma unroll
        for (int nf = 0; nf < NF; nf++) {
            int row = wm * 32 + mf * 16 + (lane >> 2);
            int col = wn * WN + nf * 8 + (lane & 3) * 2;
            stage[row * SW + col]           = c[mf][nf][0];
            stage[row * SW + col + 1]       = c[mf][nf][1];
            stage[(row + 8) * SW + col]     = c[mf][nf][2];
            stage[(row + 8) * SW + col + 1] = c[mf][nf][3];
        }
    __syncthreads();

    constexpr int CSH = (TN == 128) ? 7 : 6;
    constexpr int CMK = TN - 1;
    if (EPI == 0) {
        for (int i = tid; i < 128 * TN; i += 256) {
            int row = i >> CSH, col = i & CMK;
            outF[(size_t)(b * SPLITK + ks) * oB + (size_t)(m0 + row) * oS + n0 + col] =
                stage[row * SW + col];
        }
    } else if (EPI == 1) {
        for (int i = tid; i < 128 * TN; i += 256) {
            int row = i >> CSH, col = i & CMK;
            float v = fmaxf(stage[row * SW + col] + bias[m0 + row], 0.f);
            size_t idx = (size_t)b * (CC * NN) + (size_t)(m0 + row) * NN + n0 + col;
            bf16 h = __float2bfloat16(v);
            oHi[idx] = h; oLo[idx] = __float2bfloat16(v - __bfloat162float(h));
            stage[row * SW + col] = v;
        }
        __syncthreads();
        for (int i = tid; i < 128 * TN; i += 256) {
            int row = i & 127, col = i >> 7;   // row over 128 (c-dim), col over TN (n-dim)
            float v = stage[row * SW + col];
            size_t idx = (size_t)b * (NN * CC) + (size_t)(n0 + col) * CC + m0 + row;
            bf16 h = __float2bfloat16(v);
            tHi[idx] = h; tLo[idx] = __float2bfloat16(v - __bfloat162float(h));
        }
    } else if (EPI == 2) {
        for (int i = tid; i < 128 * TN; i += 256) {
            int row = i >> CSH, col = i & CMK;
            float v = fmaxf(stage[row * SW + col] + bias[n0 + col], 0.f);
            size_t idx = (size_t)b * (NN * CC) + (size_t)(m0 + row) * CC + n0 + col;
            bf16 h = __float2bfloat16(v);
            oHi[idx] = h; oLo[idx] = __float2bfloat16(v - __bfloat162float(h));
        }
    } else {
        float a = sH[0], s = sS[0];
        for (int i = tid; i < 128 * TN; i += 256) {
            int row = i >> CSH, col = i & CMK;
            size_t idx = (size_t)b * oB + (size_t)(m0 + row) * oS + n0 + col;
            outF[idx] = fmaxf(a * stage[row * SW + col] + s * Xres[idx], 0.f);
        }
    }
}

// -------- SIMT helpers (unchanged numerics) --------
__global__ void k_norm_bases(const float* __restrict__ b0) {
    int b = blockIdx.x;
    __shared__ float part[8][64];
    __shared__ float inv[64];
    int r = threadIdx.x & 63, g = threadIdx.x >> 6;
    float s = 0.f;
    for (int d = g; d < CC; d += 8) { float v = b0[((size_t)b * CC + d) * RR + r]; s += v * v; }
    part[g][r] = s;
    __syncthreads();
    if (g == 0) {
        float t = 0.f;
        #pragma unroll
        for (int i = 0; i < 8; i++) t += part[i][r];
        inv[r] = 1.0f / fmaxf(sqrtf(t), 1e-12f);
    }
    __syncthreads();
    for (int d = g; d < CC; d += 8) {
        size_t i = ((size_t)b * CC + d) * RR + r;
        g_bases[i] = b0[i] * inv[r];
    }
}

__global__ void k_softmax() {
    int w = (blockIdx.x * blockDim.x + threadIdx.x) >> 5, lane = threadIdx.x & 31;
    if (w >= BATCH * NN) return;
    const float* row = g_xtb + (size_t)w * RR;
    float v0 = row[lane], v1 = row[lane + 32];
    float m = fmaxf(v0, v1);
    #pragma unroll
    for (int o = 16; o; o >>= 1) m = fmaxf(m, __shfl_xor_sync(~0u, m, o));
    float e0 = expf(v0 - m), e1 = expf(v1 - m), s = e0 + e1;
    #pragma unroll
    for (int o = 16; o; o >>= 1) s += __shfl_xor_sync(~0u, s, o);
    float inv = 1.0f / s;
    float* orow = g_coef + (size_t)w * RR;
    orow[lane] = e0 * inv; orow[lane + 32] = e1 * inv;
}

__global__ void __launch_bounds__(256) k_ata(const float* __restrict__ Mb, size_t mS,
                                             int kPB, float* __restrict__ out, int nsp) {
    int sp = blockIdx.x, b = blockIdx.y;
    const float* M = Mb + (size_t)b * mS + (size_t)sp * kPB * RR;
    __shared__ float S[64][64];
    int t = threadIdx.x, rI = (t & 15) * 4, sI = (t >> 4) * 4;
    float acc[4][4] = {};
    for (int k0 = 0; k0 < kPB; k0 += 64) {
        #pragma unroll
        for (int p = 0; p < 4; p++) {
            int kr = (t >> 4) + p * 16;
            *(float4*)&S[kr][(t & 15) * 4] = *(const float4*)(M + (size_t)(k0 + kr) * RR + (t & 15) * 4);
        }
        __syncthreads();
        #pragma unroll
        for (int k = 0; k < 64; k++) {
            float4 av = *(const float4*)&S[k][rI];
            float4 bv = *(const float4*)&S[k][sI];
            float a[4] = {av.x, av.y, av.z, av.w}, bb[4] = {bv.x, bv.y, bv.z, bv.w};
            #pragma unroll
            for (int i = 0; i < 4; i++)
                #pragma unroll
                for (int j = 0; j < 4; j++) acc[i][j] = fmaf(a[i], bb[j], acc[i][j]);
        }
        __syncthreads();
    }
    float* o = out + ((size_t)b * nsp + sp) * (RR * RR);
    #pragma unroll
    for (int i = 0; i < 4; i++)
        *(float4*)&o[(size_t)(rI + i) * RR + sI] = make_float4(acc[i][0], acc[i][1], acc[i][2], acc[i][3]);
}

__global__ void k_reduce(const float* __restrict__ in, float* __restrict__ out, int sz, int nsp) {
    int idx = blockIdx.x * blockDim.x + threadIdx.x;
    if (idx >= BATCH * sz) return;
    int b = idx / sz, i = idx - b * sz;
    const float* p = in + (size_t)b * nsp * sz + i;
    float s = 0.f;
    for (int k = 0; k < nsp; k++) s += p[(size_t)k * sz];
    out[(size_t)b * sz + i] = s;
}

__global__ void __launch_bounds__(512) k_mu(float* __restrict__ M, const float* __restrict__ num,
                                            const float* __restrict__ sq, int rows) {
    int b = blockIdx.y, n0 = blockIdx.x * 8;
    __shared__ float sB[64][65];
    __shared__ float sc[8][64];
    int t = threadIdx.x;
    const float* q = sq + (size_t)b * RR * RR;
    for (int i = t; i < RR * RR; i += 512) sB[i >> 6][i & 63] = q[i];
    int rr = t >> 6, r = t & 63;
    size_t base = ((size_t)b * rows + n0 + rr) * RR;
    float cv = M[base + r];
    sc[rr][r] = cv;
    __syncthreads();
    float den = EPSV;
    #pragma unroll
    for (int s = 0; s < 64; s++) den = fmaf(sc[rr][s], sB[s][r], den);
    M[base + r] = cv * num[base + r] / den;
}

__global__ void k_cvt(const float* __restrict__ s, bf16* __restrict__ hi, bf16* __restrict__ lo, int n) {
    int i = blockIdx.x * 256 + threadIdx.x;
    if (i >= n) return;
    float v = s[i];
    bf16 h = __float2bfloat16(v);
    hi[i] = h; lo[i] = __float2bfloat16(v - __bfloat162float(h));
}

// fp32 [rows][cols] -> bf16 hi/lo transposed [cols][rows], batch z
__global__ void k_tcvt(const float* __restrict__ src, bf16* __restrict__ dh, bf16* __restrict__ dl,
                       int rows, int cols) {
    __shared__ float t[32][33];
    int b = blockIdx.z;
    size_t sb = (size_t)b * rows * cols;
    int r0 = blockIdx.y * 32, c0 = blockIdx.x * 32;
    int tx = threadIdx.x & 31, ty = threadIdx.x >> 5;
    #pragma unroll
    for (int p = 0; p < 4; p++)
        t[ty + p * 8][tx] = src[sb + (size_t)(r0 + ty + p * 8) * cols + c0 + tx];
    __syncthreads();
    #pragma unroll
    for (int p = 0; p < 4; p++) {
        float v = t[tx][ty + p * 8];
        size_t o = sb + (size_t)(c0 + ty + p * 8) * rows + r0 + tx;
        bf16 h = __float2bfloat16(v);
        dh[o] = h; dl[o] = __float2bfloat16(v - __bfloat162float(h));
    }
}

// Wb[b] = W_cheese @ bases[b]  [512][64] -> bf16 pairs (k-major [c2][r])
__global__ void __launch_bounds__(256) k_wb(const float* __restrict__ Wc) {
    int b = blockIdx.y, m0 = blockIdx.x * 64;
    __shared__ float Ws[64][65];
    __shared__ float Bs[64][64];
    int t = threadIdx.x, mI = (t & 15) * 4, rI = (t >> 4) * 4;
    float acc[4][4] = {};
    for (int k0 = 0; k0 < CC; k0 += 64) {
        #pragma unroll
        for (int p = 0; p < 16; p++) {
            int lin = t + p * 256;
            Ws[lin >> 6][lin & 63] = Wc[(size_t)(m0 + (lin >> 6)) * CC + k0 + (lin & 63)];
            Bs[lin >> 6][lin & 63] = g_bases[((size_t)b * CC + k0 + (lin >> 6)) * RR + (lin & 63)];
        }
        __syncthreads();
        #pragma unroll
        for (int k = 0; k < 64; k++)
            #pragma unroll
            for (int i = 0; i < 4; i++)
                #pragma unroll
                for (int j = 0; j < 4; j++)
                    acc[i][j] = fmaf(Ws[mI + i][k], Bs[k][rI + j], acc[i][j]);
        __syncthreads();
    }
    #pragma unroll
    for (int i = 0; i < 4; i++)
        #pragma unroll
        for (int j = 0; j < 4; j++) {
            float v = acc[i][j];
            size_t idx = ((size_t)b * CC + m0 + mI + i) * RR + rI + j;
            bf16 h = __float2bfloat16(v);
            g_Wbh[idx] = h; g_Wbl[idx] = __float2bfloat16(v - __bfloat162float(h));
        }
}

#define GSA(p, s) cudaGetSymbolAddress((void**)&p, s)

extern "C" void kernel_launch(void* const* d_in, const int* in_sizes, int n_in,
                              void* d_out, int out_size) {
    const float* x        = (const float*)d_in[0];
    const float* bases0   = (const float*)d_in[1];
    const float* w_lower  = (const float*)d_in[2];
    const float* b_lower  = (const float*)d_in[3];
    const float* w_cheese = (const float*)d_in[4];
    const float* b_cheese = (const float*)d_in[5];
    const float* w_upper  = (const float*)d_in[6];
    const float* c_short  = (const float*)d_in[7];
    const float* c_ham    = (const float*)d_in[8];
    float* out = (float*)d_out;

    float *bases, *coef, *xtb, *xc, *btb, *ctc, *ctcp, *xcp;
    GSA(bases, g_bases); GSA(coef, g_coef); GSA(xtb, g_xtb); GSA(xc, g_xc);
    GSA(btb, g_btb); GSA(ctc, g_ctc); GSA(ctcp, g_ctcp); GSA(xcp, g_xcp);
    bf16 *WLh, *WLl, *WUh, *WUl, *Xth, *Xtl, *Hh, *Hl, *Hth, *Htl, *H2h, *H2l;
    bf16 *cTh, *cTl, *Ch, *Cl, *bTh, *bTl, *Wbh, *Wbl;
    GSA(WLh, g_WLh); GSA(WLl, g_WLl); GSA(WUh, g_WUh); GSA(WUl, g_WUl);
    GSA(Xth, g_Xth); GSA(Xtl, g_Xtl); GSA(Hh, g_Hh); GSA(Hl, g_Hl);
    GSA(Hth, g_Hth); GSA(Htl, g_Htl); GSA(H2h, g_H2h); GSA(H2l, g_H2l);
    GSA(cTh, g_cTh); GSA(cTl, g_cTl); GSA(Ch, g_Ch); GSA(Cl, g_Cl);
    GSA(bTh, g_bTh); GSA(bTl, g_bTl); GSA(Wbh, g_Wbh); GSA(Wbl, g_Wbl);

    const int SM128 = 2 * 2 * (128 + 128) * 40 * 2;  // 81920
    const int SM64  = 2 * 2 * (128 + 64) * 40 * 2;   // 61440
    cudaFuncSetAttribute((void*)k_mma<128, 1, 1>, cudaFuncAttributeMaxDynamicSharedMemorySize, SM128);
    cudaFuncSetAttribute((void*)k_mma<128, 1, 2>, cudaFuncAttributeMaxDynamicSharedMemorySize, SM128);
    cudaFuncSetAttribute((void*)k_mma<128, 1, 3>, cudaFuncAttributeMaxDynamicSharedMemorySize, SM128);
    cudaFuncSetAttribute((void*)k_mma<64, 1, 0>,  cudaFuncAttributeMaxDynamicSharedMemorySize, SM64);
    cudaFuncSetAttribute((void*)k_mma<64, 8, 0>,  cudaFuncAttributeMaxDynamicSharedMemorySize, SM64);

    // conversions
    k_cvt<<<(CC * CC + 255) / 256, 256>>>(w_lower, WLh, WLl, CC * CC);
    k_cvt<<<(CC * CC + 255) / 256, 256>>>(w_upper, WUh, WUl, CC * CC);
    k_tcvt<<<dim3(NN / 32, CC / 32, BATCH), 256>>>(x, Xth, Xtl, CC, NN);
    k_norm_bases<<<BATCH, 512>>>(bases0);
    k_tcvt<<<dim3(RR / 32, CC / 32, BATCH), 256>>>(bases, bTh, bTl, CC, RR);

    // H = relu(WL @ X + b)  -> H pairs [c][n] + Ht pairs [n][c]
    k_mma<128, 1, 1><<<dim3(32, 4, BATCH), 256, SM128>>>(
        WLh, WLl, 0, CC, Xth, Xtl, (size_t)NN * CC, CC, CC,
        nullptr, 0, 0, Hh, Hl, b_lower, Hth, Htl, nullptr, nullptr, nullptr);

    // xtb = Ht @ bT'  [n][r]
    k_mma<64, 1, 0><<<dim3(1, 32, BATCH), 256, SM64>>>(
        Hth, Htl, (size_t)NN * CC, CC, bTh, bTl, (size_t)RR * CC, CC, CC,
        xtb, (size_t)NN * RR, RR, nullptr, nullptr, nullptr, nullptr, nullptr, nullptr, nullptr, nullptr);
    k_softmax<<<(BATCH * NN) / 8, 256>>>();

    for (int it = 0; it < NSTEPS; it++) {
        if (it > 0)
            k_mma<64, 1, 0><<<dim3(1, 32, BATCH), 256, SM64>>>(
                Hth, Htl, (size_t)NN * CC, CC, bTh, bTl, (size_t)RR * CC, CC, CC,
                xtb, (size_t)NN * RR, RR, nullptr, nullptr, nullptr, nullptr, nullptr, nullptr, nullptr, nullptr);
        k_ata<<<dim3(1, BATCH), 256>>>(bases, (size_t)CC * RR, CC, btb, 1);
        k_mu<<<dim3(NN / 8, BATCH), 512>>>(coef, xtb, btb, NN);
        k_tcvt<<<dim3(RR / 32, NN / 32, BATCH), 256>>>(coef, cTh, cTl, NN, RR);
        // xc = H @ cT'  [d][r], K = NN split 8
        k_mma<64, 8, 0><<<dim3(8, 4, BATCH), 256, SM64>>>(
            Hh, Hl, (size_t)CC * NN, NN, cTh, cTl, (size_t)RR * NN, NN, NN / 8,
            xcp, (size_t)CC * RR, RR, nullptr, nullptr, nullptr, nullptr, nullptr, nullptr, nullptr, nullptr);
        k_reduce<<<(BATCH * CC * RR + 255) / 256, 256>>>(xcp, xc, CC * RR, 8);
        k_ata<<<dim3(16, BATCH), 256>>>(coef, (size_t)NN * RR, 256, ctcp, 16);
        k_reduce<<<(BATCH * RR * RR + 255) / 256, 256>>>(ctcp, ctc, RR * RR, 16);
        k_mu<<<dim3(CC / 8, BATCH), 512>>>(bases, xc, ctc, CC);
        k_tcvt<<<dim3(RR / 32, CC / 32, BATCH), 256>>>(bases, bTh, bTl, CC, RR);
    }
    // refine coef
    k_mma<64, 1, 0><<<dim3(1, 32, BATCH), 256, SM64>>>(
        Hth, Htl, (size_t)NN * CC, CC, bTh, bTl, (size_t)RR * CC, CC, CC,
        xtb, (size_t)NN * RR, RR, nullptr, nullptr, nullptr, nullptr, nullptr, nullptr, nullptr, nullptr);
    k_ata<<<dim3(1, BATCH), 256>>>(bases, (size_t)CC * RR, CC, btb, 1);
    k_mu<<<dim3(NN / 8, BATCH), 512>>>(coef, xtb, btb, NN);

    // fused cheese: H2t[n][c2] = relu(coef @ Wb^T + b_cheese), Wb = Wc @ bases
    k_cvt<<<(BATCH * NN * RR + 255) / 256, 256>>>(coef, Ch, Cl, BATCH * NN * RR);
    k_wb<<<dim3(CC / 64, BATCH), 256>>>(w_cheese);
    k_mma<128, 1, 2><<<dim3(4, 32, BATCH), 256, SM128>>>(
        Ch, Cl, (size_t)NN * RR, RR, Wbh, Wbl, (size_t)CC * RR, RR, RR,
        nullptr, 0, 0, H2h, H2l, b_cheese, nullptr, nullptr, nullptr, nullptr, nullptr);
    // out = relu(c_ham * (WU @ H2) + c_short * x)
    k_mma<128, 1, 3><<<dim3(32, 4, BATCH), 256, SM128>>>(
        WUh, WUl, 0, CC, H2h, H2l, (size_t)NN * CC, CC, CC,
        out, (size_t)CC * NN, NN, nullptr, nullptr, nullptr, nullptr, nullptr, x, c_ham, c_short);
    (void)in_sizes; (void)n_in; (void)out_size;
}